// round 3
// baseline (speedup 1.0000x reference)
#include <cuda_runtime.h>
#include <cstdint>

#define THRESH 1.25f

constexpr int B    = 16;
constexpr int CIN  = 8192;   // 64*64*2
constexpr int CHID = 512;
constexpr int COUT = 100;
constexpr int T    = 300;
constexpr int NW0  = CIN / 32;   // 256 words per (b,t)
constexpr int NW1  = CHID / 32;  // 16 words per (b,t)

// ---------------- scratch (static device globals; allocation-free) -------------
__device__ __align__(256) float    d_WT1[CIN * CHID];     // 16 MB  [i][o]
__device__ __align__(256) float    d_WT2[CHID * CHID];    // 1 MB   [i][o]
__device__ __align__(256) float    d_WT3[CHID * 128];     // 256 KB [i][o pad 128]
__device__ __align__(256) float    d_scale1[CHID];
__device__ __align__(256) float    d_scale2[CHID];
__device__ __align__(256) float    d_scale3[128];
__device__ __align__(256) unsigned d_bits0[T * B * NW0];  // input spikes [t][b][w]
__device__ __align__(256) unsigned d_bits1[T * B * NW1];
__device__ __align__(256) unsigned d_bits2[T * B * NW1];
__device__ __align__(256) float    d_zpart[4][T * B * CHID]; // 39 MB layer-1 partials
__device__ __align__(256) float    d_z [T * B * CHID];    // [t][b][o]
__device__ __align__(256) float    d_z3[T * B * COUT];

// ---------------- row norms: scale[o] = g[o] / ||v[o,:]|| ----------------------
template <int L>
__global__ void row_norm(const float* __restrict__ v, const float* __restrict__ g)
{
    constexpr int NI = (L == 0) ? CIN : CHID;
    float* scale = (L == 0) ? d_scale1 : (L == 1) ? d_scale2 : d_scale3;
    int r = blockIdx.x;
    const float* row = v + (size_t)r * NI;
    float s = 0.f;
    for (int i = threadIdx.x; i < NI; i += 256) { float x = row[i]; s = fmaf(x, x, s); }
    #pragma unroll
    for (int d = 16; d > 0; d >>= 1) s += __shfl_down_sync(0xffffffffu, s, d);
    __shared__ float red[8];
    int lane = threadIdx.x & 31, w = threadIdx.x >> 5;
    if (lane == 0) red[w] = s;
    __syncthreads();
    if (threadIdx.x == 0) {
        float tot = 0.f;
        #pragma unroll
        for (int j = 0; j < 8; j++) tot += red[j];
        scale[r] = g[r] / sqrtf(tot);
    }
}

// ---------------- transpose + scale: WT[i][o] = v[o][i] * scale[o] -------------
template <int L>
__global__ void wnorm_transpose(const float* __restrict__ v)
{
    constexpr int NI      = (L == 0) ? CIN : CHID;
    constexpr int OSTRIDE = (L == 2) ? 128 : CHID;
    constexpr int NOV     = (L == 2) ? COUT : CHID;
    float* wt = (L == 0) ? d_WT1 : (L == 1) ? d_WT2 : d_WT3;
    const float* scale = (L == 0) ? d_scale1 : (L == 1) ? d_scale2 : d_scale3;

    __shared__ float tile[64][65];
    int i0 = blockIdx.x * 64, o0 = blockIdx.y * 64;
    int tid = threadIdx.x;
    int oy = tid >> 4;
    int ix = (tid & 15) * 4;

    #pragma unroll
    for (int k = 0; k < 4; k++) {
        int ol = oy + k * 16;
        int o  = o0 + ol;
        float4 val = make_float4(0.f, 0.f, 0.f, 0.f);
        if (o < NOV) val = *(const float4*)&v[(size_t)o * NI + i0 + ix];
        tile[ix + 0][ol] = val.x;
        tile[ix + 1][ol] = val.y;
        tile[ix + 2][ol] = val.z;
        tile[ix + 3][ol] = val.w;
    }
    __syncthreads();

    int iy = tid >> 4;
    int ox = (tid & 15) * 4;
    float4 sc;
    sc.x = (o0 + ox + 0 < NOV) ? scale[o0 + ox + 0] : 0.f;
    sc.y = (o0 + ox + 1 < NOV) ? scale[o0 + ox + 1] : 0.f;
    sc.z = (o0 + ox + 2 < NOV) ? scale[o0 + ox + 2] : 0.f;
    sc.w = (o0 + ox + 3 < NOV) ? scale[o0 + ox + 3] : 0.f;
    #pragma unroll
    for (int k = 0; k < 4; k++) {
        int il = iy + k * 16;
        float4 w;
        w.x = tile[il][ox + 0] * sc.x;
        w.y = tile[il][ox + 1] * sc.y;
        w.z = tile[il][ox + 2] * sc.z;
        w.w = tile[il][ox + 3] * sc.w;
        *(float4*)&wt[(size_t)(i0 + il) * OSTRIDE + o0 + ox] = w;
    }
}

// ---------------- bitpack input spikes [b][i][t] -> bits [t][b][i/32] ----------
__global__ void bitpack_in(const float* __restrict__ spike)
{
    int warpId = (blockIdx.x * blockDim.x + threadIdx.x) >> 5;
    int lane   = threadIdx.x & 31;
    int tc = warpId % 10;
    int ig = (warpId / 10) % (CIN / 32);
    int b  = warpId / (10 * (CIN / 32));
    int i  = ig * 32 + lane;
    int t0 = tc * 32;

    const float4* sp4 = (const float4*)(spike + ((size_t)b * CIN + i) * T);
    float4 v[8];
    #pragma unroll
    for (int j = 0; j < 8; j++) {
        int tt = t0 + 4 * j;
        v[j] = (tt < T) ? sp4[tt >> 2] : make_float4(0.f, 0.f, 0.f, 0.f);
    }
    #pragma unroll
    for (int j = 0; j < 8; j++) {
        float4 q = v[j];
        unsigned m0 = __ballot_sync(0xffffffffu, q.x > 0.5f);
        unsigned m1 = __ballot_sync(0xffffffffu, q.y > 0.5f);
        unsigned m2 = __ballot_sync(0xffffffffu, q.z > 0.5f);
        unsigned m3 = __ballot_sync(0xffffffffu, q.w > 0.5f);
        int tb = t0 + 4 * j;
        if (lane == 4 * j + 0 && tb + 0 < T) d_bits0[(size_t)(tb + 0) * (B * NW0) + b * NW0 + ig] = m0;
        if (lane == 4 * j + 1 && tb + 1 < T) d_bits0[(size_t)(tb + 1) * (B * NW0) + b * NW0 + ig] = m1;
        if (lane == 4 * j + 2 && tb + 2 < T) d_bits0[(size_t)(tb + 2) * (B * NW0) + b * NW0 + ig] = m2;
        if (lane == 4 * j + 3 && tb + 3 < T) d_bits0[(size_t)(tb + 3) * (B * NW0) + b * NW0 + ig] = m3;
    }
}

// ---------------- layer-1 W-stationary smem SpMM --------------------------------
// grid 256: block = (o-chunk 128, batch b, i-quarter 2048)
// 640 threads = 20 warps; warp w owns timesteps [w*15, w*15+15)
// stages of 128 W-rows x 128 o (64 KB) double-buffered via cp.async
__device__ __forceinline__ void cpasync16(uint32_t saddr, const void* g)
{
    asm volatile("cp.async.cg.shared.global [%0], [%1], 16;" :: "r"(saddr), "l"(g));
}

__global__ __launch_bounds__(640, 1) void spmm1()
{
    extern __shared__ float4 sW[];   // 2 buffers x 4096 float4 (64 KB each)

    int oc = blockIdx.x & 3;
    int b  = (blockIdx.x >> 2) & 15;
    int q  = blockIdx.x >> 6;
    int o0 = oc * 128;
    int ibase = q * 2048;
    int wq4 = q * 16;               // uint4 offset of this i-quarter in a bits row

    int tid = threadIdx.x, lane = tid & 31, wid = tid >> 5;
    int t0 = wid * 15;              // 20*15 = 300 exactly

    const uint4* bits4 = (const uint4*)d_bits0;   // row (t*16+b) has 64 uint4
    uint32_t sbase = (uint32_t)__cvta_generic_to_shared(sW);

    float4 acc[15];
    #pragma unroll
    for (int j = 0; j < 15; j++) acc[j] = make_float4(0.f, 0.f, 0.f, 0.f);

    // issue stage s into buffer buf
    #define ISSUE_STAGE(s, buf)                                                   \
    {                                                                             \
        const float* gsrc = d_WT1 + (size_t)(ibase + (s) * 128) * CHID + o0;      \
        uint32_t dst = sbase + (buf) * 65536u;                                    \
        for (int k = tid; k < 4096; k += 640) {                                   \
            int r = k >> 5, c = k & 31;                                           \
            cpasync16(dst + (unsigned)k * 16u, gsrc + r * CHID + c * 4);          \
        }                                                                         \
        asm volatile("cp.async.commit_group;");                                   \
    }

    ISSUE_STAGE(0, 0);

    for (int s = 0; s < 16; s++) {
        if (s + 1 < 16) {
            ISSUE_STAGE(s + 1, (s + 1) & 1);
            asm volatile("cp.async.wait_group 1;");
        } else {
            asm volatile("cp.async.wait_group 0;");
        }
        __syncthreads();
        const float4* sb = sW + (size_t)(s & 1) * 4096;

        #pragma unroll
        for (int tl = 0; tl < 15; tl++) {
            int t = t0 + tl;
            uint4 bw = __ldg(&bits4[(size_t)(t * 16 + b) * 64 + wq4 + s]);
            unsigned mw0 = bw.x, mw1 = bw.y, mw2 = bw.z, mw3 = bw.w;
            while (mw0) {
                int bp = __ffs((int)mw0) - 1; mw0 &= mw0 - 1;
                float4 w = sb[(0 * 32 + bp) * 32 + lane];
                acc[tl].x += w.x; acc[tl].y += w.y; acc[tl].z += w.z; acc[tl].w += w.w;
            }
            while (mw1) {
                int bp = __ffs((int)mw1) - 1; mw1 &= mw1 - 1;
                float4 w = sb[(1 * 32 + bp) * 32 + lane];
                acc[tl].x += w.x; acc[tl].y += w.y; acc[tl].z += w.z; acc[tl].w += w.w;
            }
            while (mw2) {
                int bp = __ffs((int)mw2) - 1; mw2 &= mw2 - 1;
                float4 w = sb[(2 * 32 + bp) * 32 + lane];
                acc[tl].x += w.x; acc[tl].y += w.y; acc[tl].z += w.z; acc[tl].w += w.w;
            }
            while (mw3) {
                int bp = __ffs((int)mw3) - 1; mw3 &= mw3 - 1;
                float4 w = sb[(3 * 32 + bp) * 32 + lane];
                acc[tl].x += w.x; acc[tl].y += w.y; acc[tl].z += w.z; acc[tl].w += w.w;
            }
        }
        __syncthreads();
    }
    #undef ISSUE_STAGE

    float4* zp = (float4*)d_zpart[q];
    #pragma unroll
    for (int tl = 0; tl < 15; tl++) {
        int t = t0 + tl;
        zp[(size_t)(t * 16 + b) * 128 + oc * 32 + lane] = acc[tl];
    }
}

// fixed-order reduction of the 4 i-quarter partials
__global__ void zreduce()
{
    int i = blockIdx.x * blockDim.x + threadIdx.x;   // float4 index, n = 614400
    const float4* p0 = (const float4*)d_zpart[0];
    const float4* p1 = (const float4*)d_zpart[1];
    const float4* p2 = (const float4*)d_zpart[2];
    const float4* p3 = (const float4*)d_zpart[3];
    float4 a = p0[i], bb = p1[i], c = p2[i], d = p3[i];
    float4 o;
    o.x = ((a.x + bb.x) + c.x) + d.x;
    o.y = ((a.y + bb.y) + c.y) + d.y;
    o.z = ((a.z + bb.z) + c.z) + d.z;
    o.w = ((a.w + bb.w) + c.w) + d.w;
    ((float4*)d_z)[i] = o;
}

// ---------------- layer-2 sparse gather (hidden spikes, lower traffic) ----------
__global__ void gather_hid2()
{
    const float2* __restrict__ wt = (const float2*)d_WT2;
    int t = blockIdx.x, b = blockIdx.y;
    const unsigned* bp = d_bits1 + ((size_t)t * B + b) * NW1;

    __shared__ unsigned short sidx[NW1 * 32];
    __shared__ int wcnt[8];
    int tid = threadIdx.x, lane = tid & 31, w = tid >> 5;

    int word = w * 32 + lane;
    unsigned m = (word < NW1) ? bp[word] : 0u;
    int c = __popc(m);
    int x = c;
    #pragma unroll
    for (int d = 1; d < 32; d <<= 1) {
        int y = __shfl_up_sync(0xffffffffu, x, d);
        if (lane >= d) x += y;
    }
    if (lane == 31) wcnt[w] = x;
    __syncthreads();

    int base = 0, cnt = 0;
    #pragma unroll
    for (int j = 0; j < 8; j++) {
        int wc = wcnt[j];
        if (j < w) base += wc;
        cnt += wc;
    }
    int mybase = base + x - c;
    while (m) {
        int bpos = __ffs((int)m) - 1;
        m &= m - 1;
        sidx[mybase++] = (unsigned short)(word * 32 + bpos);
    }
    __syncthreads();

    float ax = 0.f, ay = 0.f;
    int k = 0;
    for (; k + 8 <= cnt; k += 8) {
        float2 r[8];
        #pragma unroll
        for (int u = 0; u < 8; u++) { int i = sidx[k + u]; r[u] = wt[i * 256 + tid]; }
        #pragma unroll
        for (int u = 0; u < 8; u++) { ax += r[u].x; ay += r[u].y; }
    }
    for (; k < cnt; k++) {
        float2 r0 = wt[sidx[k] * 256 + tid];
        ax += r0.x; ay += r0.y;
    }
    float2 o; o.x = ax; o.y = ay;
    ((float2*)d_z)[((size_t)t * B + b) * 256 + tid] = o;
}

// layer 3: 100 outputs (padded to 128)
__global__ void gather_out()
{
    int t = blockIdx.x, b = blockIdx.y;
    const unsigned* bp = d_bits2 + ((size_t)t * B + b) * NW1;

    __shared__ unsigned short sidx[NW1 * 32];
    __shared__ int scount;
    int tid = threadIdx.x, lane = tid & 31;

    if (tid < 32) {
        unsigned m = (lane < NW1) ? bp[lane] : 0u;
        int c = __popc(m);
        int x = c;
        #pragma unroll
        for (int d = 1; d < 32; d <<= 1) {
            int y = __shfl_up_sync(0xffffffffu, x, d);
            if (lane >= d) x += y;
        }
        int base = x - c;
        while (m) {
            int bpos = __ffs((int)m) - 1;
            m &= m - 1;
            sidx[base++] = (unsigned short)(lane * 32 + bpos);
        }
        if (lane == 31) scount = x;
    }
    __syncthreads();

    int cnt = scount;
    float acc = 0.f;
    int k = 0;
    for (; k + 8 <= cnt; k += 8) {
        float r[8];
        #pragma unroll
        for (int u = 0; u < 8; u++) { int i = sidx[k + u]; r[u] = d_WT3[i * 128 + tid]; }
        #pragma unroll
        for (int u = 0; u < 8; u++) acc += r[u];
    }
    for (; k < cnt; k++) acc += d_WT3[sidx[k] * 128 + tid];

    if (tid < COUT) d_z3[((size_t)t * B + b) * COUT + tid] = acc;
}

// ---------------- LIF recurrence over T, hidden layers -> bitmasks -------------
template <int L>
__global__ void lif_hid(const float* __restrict__ cds, const float* __restrict__ vds)
{
    unsigned* bitsout = (L == 0) ? d_bits1 : d_bits2;
    int gid  = blockIdx.x * blockDim.x + threadIdx.x;
    int lane = threadIdx.x & 31;
    float a  = 1.f - cds[L];
    float bb = 1.f - vds[L];
    float cur = 0.f, volt = 0.f;

    float zbuf[4];
    #pragma unroll
    for (int j = 0; j < 4; j++) zbuf[j] = d_z[(size_t)j * (B * CHID) + gid];

    #pragma unroll 4
    for (int t = 0; t < T; t++) {
        float zt = zbuf[t & 3];
        int tp = t + 4;
        zbuf[t & 3] = (tp < T) ? d_z[(size_t)tp * (B * CHID) + gid] : 0.f;
        cur  = fmaf(a, cur, zt);
        volt = fmaf(bb, volt, cur);
        bool s = volt >= THRESH;
        unsigned msk = __ballot_sync(0xffffffffu, s);
        volt = s ? 0.f : volt;
        if (lane == 0) bitsout[(size_t)t * (B * NW1) + (gid >> 5)] = msk;
    }
}

// ---------------- LIF output layer -> d_out [b][c][t] float --------------------
__global__ void lif_out(const float* __restrict__ cds, const float* __restrict__ vds,
                        float* __restrict__ out)
{
    int gid = blockIdx.x * blockDim.x + threadIdx.x;
    if (gid >= B * COUT) return;
    int b = gid / COUT, c = gid % COUT;
    float a  = 1.f - cds[2];
    float bb = 1.f - vds[2];
    float cur = 0.f, volt = 0.f;
    float* orow = out + ((size_t)b * COUT + c) * T;

    float zbuf[4];
    #pragma unroll
    for (int j = 0; j < 4; j++) zbuf[j] = d_z3[(size_t)j * (B * COUT) + gid];

    #pragma unroll 4
    for (int t = 0; t < T; t++) {
        float zt = zbuf[t & 3];
        int tp = t + 4;
        zbuf[t & 3] = (tp < T) ? d_z3[(size_t)tp * (B * COUT) + gid] : 0.f;
        cur  = fmaf(a, cur, zt);
        volt = fmaf(bb, volt, cur);
        bool s = volt >= THRESH;
        volt = s ? 0.f : volt;
        orow[t] = s ? 1.0f : 0.0f;
    }
}

// ---------------- launch ---------------------------------------------------------
extern "C" void kernel_launch(void* const* d_in, const int* in_sizes, int n_in,
                              void* d_out, int out_size)
{
    const float* spike = (const float*)d_in[0];
    const float* v1 = (const float*)d_in[1];
    const float* g1 = (const float*)d_in[2];
    const float* v2 = (const float*)d_in[3];
    const float* g2 = (const float*)d_in[4];
    const float* v3 = (const float*)d_in[5];
    const float* g3 = (const float*)d_in[6];
    const float* cds = (const float*)d_in[7];
    const float* vds = (const float*)d_in[8];
    float* out = (float*)d_out;

    cudaFuncSetAttribute(spmm1, cudaFuncAttributeMaxDynamicSharedMemorySize, 131072);

    // ordered so spmm1 sits at the launch index ncu keeps capturing
    row_norm<0><<<CHID, 256>>>(v1, g1);                       // 0
    wnorm_transpose<0><<<dim3(CIN / 64, CHID / 64), 256>>>(v1); // 1
    bitpack_in<<<(B * (CIN / 32) * 10) / 4, 128>>>(spike);    // 2
    spmm1<<<256, 640, 131072>>>();                            // 3  (hot kernel)
    row_norm<1><<<CHID, 256>>>(v2, g2);                       // 4
    row_norm<2><<<COUT, 256>>>(v3, g3);                       // 5
    wnorm_transpose<1><<<dim3(CHID / 64, CHID / 64), 256>>>(v2);
    wnorm_transpose<2><<<dim3(CHID / 64, 2), 256>>>(v3);
    zreduce<<<2400, 256>>>();
    lif_hid<0><<<(B * CHID) / 128, 128>>>(cds, vds);
    gather_hid2<<<dim3(T, B), 256>>>();
    lif_hid<1><<<(B * CHID) / 128, 128>>>(cds, vds);
    gather_out<<<dim3(T, B), 128>>>();
    lif_out<<<(B * COUT + 127) / 128, 128>>>(cds, vds, out);
}